// round 14
// baseline (speedup 1.0000x reference)
#include <cuda_runtime.h>
#include <cuda_fp16.h>
#include <cstdint>

#define BATCH 64
#define TT 256
#define CC 512
#define NHD 8
#define HD 64
#define MROWS (BATCH*TT)      // 16384
#define FF 2048
#define QKV 1536
#define ATT_SCALE 0.044194173824159216f   // 512^-0.5
#define NEGBIG (-1e9f)

// ---------------- scratch (device globals; no allocations) ----------------
__device__ __half g_ln  [MROWS*CC];
__device__ __half g_qkv [(size_t)MROWS*QKV];
__device__ __half g_qc  [MROWS*CC];                  // cross-attn Q
__device__ __half g_kvc [(size_t)MROWS*1024];        // cross-attn K|V
__device__ __half g_att [MROWS*CC];
__device__ __half g_ca  [MROWS*CC];
__device__ __half g_h   [(size_t)MROWS*FF];
__device__ __half g_wqkvs[QKV*CC];
__device__ __half g_wqkvc[QKV*CC];
__device__ __half g_wos [CC*CC];
__device__ __half g_woc [CC*CC];
__device__ __half g_wf1t[FF*CC];
__device__ __half g_wf2t[CC*FF];
__device__ float  g_x1  [MROWS*CC];
__device__ float  g_x2  [MROWS*CC];

// ---------------- helpers ----------------
__device__ __forceinline__ void mma16(float4& d, const uint32_t* a, const uint32_t* b){
    asm volatile("mma.sync.aligned.m16n8k16.row.col.f32.f16.f16.f32 "
        "{%0,%1,%2,%3}, {%4,%5,%6,%7}, {%8,%9}, {%0,%1,%2,%3};"
        : "+f"(d.x), "+f"(d.y), "+f"(d.z), "+f"(d.w)
        : "r"(a[0]), "r"(a[1]), "r"(a[2]), "r"(a[3]), "r"(b[0]), "r"(b[1]));
}
__device__ __forceinline__ void ldsm4(uint32_t* r, uint32_t addr){
    asm volatile("ldmatrix.sync.aligned.m8n8.x4.shared.b16 {%0,%1,%2,%3}, [%4];"
        : "=r"(r[0]), "=r"(r[1]), "=r"(r[2]), "=r"(r[3]) : "r"(addr));
}
__device__ __forceinline__ void ldsm4t(uint32_t* r, uint32_t addr){
    asm volatile("ldmatrix.sync.aligned.m8n8.x4.trans.shared.b16 {%0,%1,%2,%3}, [%4];"
        : "=r"(r[0]), "=r"(r[1]), "=r"(r[2]), "=r"(r[3]) : "r"(addr));
}
__device__ __forceinline__ uint32_t h2pack(float a, float b){
    __half2 h = __floats2half2_rn(a, b);
    return *reinterpret_cast<uint32_t*>(&h);
}
#define CP16(d, s) asm volatile("cp.async.cg.shared.global [%0], [%1], 16;" :: "r"(d), "l"(s))
#define CPCOMMIT() asm volatile("cp.async.commit_group;" ::: "memory")
#define CPWAIT(n)  asm volatile("cp.async.wait_group %0;" :: "n"(n) : "memory")

__device__ __forceinline__ float warpSum(float v){
    #pragma unroll
    for (int o = 16; o; o >>= 1) v += __shfl_xor_sync(0xffffffffu, v, o);
    return v;
}

// ---------------- prepass: weight transpose -> fp16 [N][K] ----------------
__global__ void wtrans8(const float* s0, const float* s1, const float* s2, const float* s3,
                        const float* s4, const float* s5, const float* s6, const float* s7,
                        __half* qkvs, __half* wos, __half* qkvc, __half* woc)
{
    int z = blockIdx.z;
    const float* src = (z==0)?s0:(z==1)?s1:(z==2)?s2:(z==3)?s3:(z==4)?s4:(z==5)?s5:(z==6)?s6:s7;
    __half* dst = (z<3) ? qkvs + (size_t)z*CC*CC
               : (z==3) ? wos
               : (z<7) ? qkvc + (size_t)(z-4)*CC*CC
               : woc;
    __shared__ float t[32][33];
    int bx = blockIdx.x*32, by = blockIdx.y*32;
    int x = threadIdx.x, y = threadIdx.y;
    #pragma unroll
    for (int i = 0; i < 32; i += 8)
        t[y+i][x] = src[(size_t)(by + y + i)*CC + bx + x];
    __syncthreads();
    #pragma unroll
    for (int i = 0; i < 32; i += 8)
        dst[(size_t)(bx + y + i)*CC + by + x] = __float2half_rn(t[x][y+i]);
}

__global__ void ttrans(const float* __restrict__ src, __half* __restrict__ dst, int R, int C)
{
    __shared__ float t[32][33];
    int bx = blockIdx.x*32, by = blockIdx.y*32;
    int x = threadIdx.x, y = threadIdx.y;
    #pragma unroll
    for (int i = 0; i < 32; i += 8)
        t[y+i][x] = src[(size_t)(by + y + i)*C + bx + x];
    __syncthreads();
    #pragma unroll
    for (int i = 0; i < 32; i += 8)
        dst[(size_t)(bx + y + i)*R + by + x] = __float2half_rn(t[x][y+i]);
}

__global__ void f2h_kernel(const float* __restrict__ src, __half* __restrict__ dst, int n4){
    int i = blockIdx.x*256 + threadIdx.x;
    if (i < n4){
        float4 v = reinterpret_cast<const float4*>(src)[i];
        reinterpret_cast<__half2*>(dst)[2*i]   = __floats2half2_rn(v.x, v.y);
        reinterpret_cast<__half2*>(dst)[2*i+1] = __floats2half2_rn(v.z, v.w);
    }
}

// ---------------- layernorm (fp16 output) ----------------
__global__ void ln_kernel(const float* __restrict__ x, const float* __restrict__ g,
                          const float* __restrict__ be, __half* __restrict__ y)
{
    int r = blockIdx.x;
    int t = threadIdx.x;
    const float4* xr = reinterpret_cast<const float4*>(x + (size_t)r*CC);
    float4 v = xr[t];
    float s  = v.x + v.y + v.z + v.w;
    float sq = v.x*v.x + v.y*v.y + v.z*v.z + v.w*v.w;

    __shared__ float rs[4], rq[4];
    int lane = t & 31, wid = t >> 5;
    s = warpSum(s); sq = warpSum(sq);
    if (lane == 0){ rs[wid] = s; rq[wid] = sq; }
    __syncthreads();
    if (t == 0){
        float a = rs[0]+rs[1]+rs[2]+rs[3];
        float b = rq[0]+rq[1]+rq[2]+rq[3];
        rs[0] = a * (1.0f/CC);
        rq[0] = b * (1.0f/CC);
    }
    __syncthreads();
    float mu  = rs[0];
    float var = rq[0] - mu*mu;
    float rstd = rsqrtf(var + 1e-5f);

    const float4* g4  = reinterpret_cast<const float4*>(g);
    const float4* be4 = reinterpret_cast<const float4*>(be);
    float4 gg = g4[t], bb = be4[t];
    __half2 o0 = __floats2half2_rn((v.x - mu)*rstd*gg.x + bb.x, (v.y - mu)*rstd*gg.y + bb.y);
    __half2 o1 = __floats2half2_rn((v.z - mu)*rstd*gg.z + bb.z, (v.w - mu)*rstd*gg.w + bb.w);
    __half2* yh = reinterpret_cast<__half2*>(y + (size_t)r*CC);
    yh[2*t]   = o0;
    yh[2*t+1] = o1;
}

// =================== fp16 mma.sync GEMM: BK=64, B [N][K], BN in {64,128} ===================
// Single barrier per chunk: CPWAIT -> syncthreads -> ISSUE(ch+2) -> mma.
template<int BN, bool BIAS, bool RELU, bool RES, bool HOUT>
__global__ __launch_bounds__(256, 2)
void gemm_h(const __half* __restrict__ A, int lda,
            const __half* __restrict__ B, int ldb,
            const float* __restrict__ bias, const float* __restrict__ res,
            void* __restrict__ Cv, int ldc, int K)
{
    constexpr int NT = BN/16;           // n8 tiles per warp
    constexpr int ABYTES = 128*128;
    constexpr int BBYTES = BN*128;
    constexpr int STAGE  = ABYTES + BBYTES;

    extern __shared__ char smp[];
    const uint32_t smem_base = (uint32_t)__cvta_generic_to_shared(smp);

    const int tid  = threadIdx.x;
    const int w    = tid >> 5, lane = tid & 31;
    const int g    = lane >> 2, c = lane & 3;
    const int row0 = blockIdx.y * 128;
    const int col0 = blockIdx.x * BN;

    float* Cf = (float*)Cv;
    __half* Ch = (__half*)Cv;

    float4 acc[2][NT];
    #pragma unroll
    for (int mt = 0; mt < 2; mt++)
        #pragma unroll
        for (int nt = 0; nt < NT; nt++)
            acc[mt][nt] = make_float4(0.f, 0.f, 0.f, 0.f);

    const int nch = K >> 6;
    const int mwb = (w & 3) * 32;
    const int nwb = (w >> 2) * (BN/2);

    const int lrow = lane & 7;
    uint32_t aBase[2], aSw[2];
    const uint32_t aKc = (uint32_t)(lane >> 4);
    #pragma unroll
    for (int mt = 0; mt < 2; mt++){
        int m = mwb + mt*16 + ((lane>>3)&1)*8 + lrow;
        aBase[mt] = (uint32_t)m * 128u;
        aSw[mt]   = (uint32_t)(m & 7);
    }
    uint32_t bBase[NT/2], bSw[NT/2];
    const uint32_t bKc = (uint32_t)((lane>>3)&1);
    #pragma unroll
    for (int ng = 0; ng < NT/2; ng++){
        int n = nwb + ng*16 + (lane>>4)*8 + lrow;
        bBase[ng] = (uint32_t)n * 128u;
        bSw[ng]   = (uint32_t)(n & 7);
    }

    #define ISSUE(ch, s) do { \
        const uint32_t sa = smem_base + (s)*STAGE; \
        const __half* Ag = A + (size_t)row0*lda + (ch)*64; \
        _Pragma("unroll") \
        for (int i = 0; i < 4; i++){ \
            int t2 = tid + 256*i; int m = t2 >> 3, c2 = t2 & 7; \
            CP16(sa + m*128 + ((c2 ^ (m & 7)) << 4), Ag + (size_t)m*lda + c2*8); \
        } \
        const uint32_t sb2 = sa + ABYTES; \
        const __half* Bg = B + (size_t)col0*ldb + (ch)*64; \
        _Pragma("unroll") \
        for (int i = 0; i < BN/32; i++){ \
            int t2 = tid + 256*i; int n = t2 >> 3, c2 = t2 & 7; \
            CP16(sb2 + n*128 + ((c2 ^ (n & 7)) << 4), Bg + (size_t)n*ldb + c2*8); \
        } \
        CPCOMMIT(); \
    } while(0)

    ISSUE(0, 0);
    ISSUE(1, 1);

    for (int ch = 0; ch < nch; ch++){
        const int p = ch % 3;
        if (ch == nch - 1) CPWAIT(0); else CPWAIT(1);
        __syncthreads();                 // data visible + all warps done with stage (ch-1)%3
        if (ch + 2 < nch) ISSUE(ch+2, (ch+2)%3);   // writes stage (ch-1)%3 — safe

        const uint32_t sA = smem_base + p*STAGE;
        const uint32_t sB = sA + ABYTES;

        #pragma unroll
        for (int ks = 0; ks < 4; ks++){
            uint32_t af[2][4], bfr[NT][2];
            #pragma unroll
            for (int mt = 0; mt < 2; mt++)
                ldsm4(af[mt], sA + aBase[mt] + ((((uint32_t)(2*ks) + aKc) ^ aSw[mt]) << 4));
            #pragma unroll
            for (int ng = 0; ng < NT/2; ng++){
                uint32_t r[4];
                ldsm4(r, sB + bBase[ng] + ((((uint32_t)(2*ks) + bKc) ^ bSw[ng]) << 4));
                bfr[2*ng  ][0] = r[0]; bfr[2*ng  ][1] = r[1];
                bfr[2*ng+1][0] = r[2]; bfr[2*ng+1][1] = r[3];
            }
            #pragma unroll
            for (int mt = 0; mt < 2; mt++)
                #pragma unroll
                for (int nt = 0; nt < NT; nt++)
                    mma16(acc[mt][nt], af[mt], bfr[nt]);
        }
    }

    #pragma unroll
    for (int mt = 0; mt < 2; mt++){
        int r0 = row0 + mwb + mt*16 + g;
        #pragma unroll
        for (int nt = 0; nt < NT; nt++){
            int cx = col0 + nwb + nt*8 + c*2;
            float4 v = acc[mt][nt];
            if (BIAS){
                float b0 = bias[cx], b1 = bias[cx+1];
                v.x += b0; v.y += b1; v.z += b0; v.w += b1;
            }
            if (RELU){
                v.x = fmaxf(v.x, 0.f); v.y = fmaxf(v.y, 0.f);
                v.z = fmaxf(v.z, 0.f); v.w = fmaxf(v.w, 0.f);
            }
            if (RES){
                float2 r1 = *reinterpret_cast<const float2*>(&res[(size_t)r0*ldc + cx]);
                float2 r2 = *reinterpret_cast<const float2*>(&res[(size_t)(r0+8)*ldc + cx]);
                v.x += r1.x; v.y += r1.y; v.z += r2.x; v.w += r2.y;
            }
            if (HOUT){
                *reinterpret_cast<__half2*>(&Ch[(size_t)r0*ldc + cx])     = __floats2half2_rn(v.x, v.y);
                *reinterpret_cast<__half2*>(&Ch[(size_t)(r0+8)*ldc + cx]) = __floats2half2_rn(v.z, v.w);
            } else {
                *reinterpret_cast<float2*>(&Cf[(size_t)r0*ldc + cx])     = make_float2(v.x, v.y);
                *reinterpret_cast<float2*>(&Cf[(size_t)(r0+8)*ldc + cx]) = make_float2(v.z, v.w);
            }
        }
    }
    #undef ISSUE
}

// =================== fused attention: QK^T + mask + softmax + P@V ===================
#define AT_STAGE (128*64 + 256*64)
#define AT_OFF_V (2*AT_STAGE)
#define AT_OFF_R (AT_OFF_V + 256*128)
#define AT_SMEM  (AT_OFF_R + 2048)
__global__ __launch_bounds__(256, 1)
void attn(const __half* __restrict__ Q, int ldq,
          const __half* __restrict__ Kmat, const __half* __restrict__ V, int ldkv,
          const int* __restrict__ mask, __half* __restrict__ O, int causal)
{
    constexpr int NT = 16;
    extern __shared__ char smp[];
    const uint32_t smem_base = (uint32_t)__cvta_generic_to_shared(smp);

    const int tid  = threadIdx.x;
    const int w    = tid >> 5, lane = tid & 31;
    const int g    = lane >> 2, c = lane & 3;
    const int row0 = blockIdx.x * 128;
    {
        const long long zb = blockIdx.y >> 3, zh = blockIdx.y & 7;
        Q    += zb*(long long)TT*ldq  + zh*HD;
        Kmat += zb*(long long)TT*ldkv + zh*HD;
        V    += zb*(long long)TT*ldkv + zh*HD;
        mask += zb*(long long)TT*TT;
        O    += zb*(long long)TT*CC + zh*HD;
    }

    float4 acc[2][NT];
    #pragma unroll
    for (int mt = 0; mt < 2; mt++)
        #pragma unroll
        for (int nt = 0; nt < NT; nt++)
            acc[mt][nt] = make_float4(0.f, 0.f, 0.f, 0.f);

    const int mwb = (w & 3) * 32;
    const int nwb = (w >> 2) * 128;

    const int lrow = lane & 7;
    uint32_t aBase[2], aSw[2];
    const uint32_t aKc = (uint32_t)(lane >> 4);
    #pragma unroll
    for (int mt = 0; mt < 2; mt++){
        int m = mwb + mt*16 + ((lane>>3)&1)*8 + lrow;
        aBase[mt] = (uint32_t)m * 64u;
        aSw[mt]   = (uint32_t)((m>>1)&3);
    }
    uint32_t bBase[8], bSw[8];
    const uint32_t bKc = (uint32_t)((lane>>3)&1);
    #pragma unroll
    for (int ng = 0; ng < 8; ng++){
        int n = nwb + ng*16 + (lane>>4)*8 + lrow;
        bBase[ng] = (uint32_t)n * 64u;
        bSw[ng]   = (uint32_t)((n>>1)&3);
    }

    #define QISSUE(ch, s) do { \
        const uint32_t sa = smem_base + (s)*AT_STAGE; \
        const __half* Ag = Q + (size_t)row0*ldq + (ch)*32; \
        _Pragma("unroll") \
        for (int i = 0; i < 2; i++){ \
            int t2 = tid + 256*i; int m = t2 >> 2, c2 = t2 & 3; \
            CP16(sa + m*64 + ((c2 ^ ((m>>1)&3)) << 4), Ag + (size_t)m*ldq + c2*8); \
        } \
        const uint32_t sb2 = sa + 128*64; \
        const __half* Bg = Kmat + (ch)*32; \
        _Pragma("unroll") \
        for (int i = 0; i < 4; i++){ \
            int t2 = tid + 256*i; int n = t2 >> 2, c2 = t2 & 3; \
            CP16(sb2 + n*64 + ((c2 ^ ((n>>1)&3)) << 4), Bg + (size_t)n*ldkv + c2*8); \
        } \
        CPCOMMIT(); \
    } while(0)

    QISSUE(0, 0);
    {
        #pragma unroll
        for (int i = 0; i < 8; i++){
            int idx = tid + 256*i;
            int t2 = idx >> 3, c2 = idx & 7;
            CP16(smem_base + AT_OFF_V + t2*128 + ((c2 ^ (t2 & 7)) << 4),
                 V + (size_t)t2*ldkv + c2*8);
        }
        CPCOMMIT();
    }
    QISSUE(1, 1);

    #pragma unroll
    for (int ch = 0; ch < 2; ch++){
        if (ch == 0) CPWAIT(2); else CPWAIT(0);
        __syncthreads();
        const uint32_t sA = smem_base + ch*AT_STAGE;
        const uint32_t sB = sA + 128*64;
        #pragma unroll
        for (int ks = 0; ks < 2; ks++){
            uint32_t af[2][4], bfr[NT][2];
            #pragma unroll
            for (int mt = 0; mt < 2; mt++)
                ldsm4(af[mt], sA + aBase[mt] + ((((uint32_t)(2*ks) + aKc) ^ aSw[mt]) << 4));
            #pragma unroll
            for (int ng = 0; ng < 8; ng++){
                uint32_t r[4];
                ldsm4(r, sB + bBase[ng] + ((((uint32_t)(2*ks) + bKc) ^ bSw[ng]) << 4));
                bfr[2*ng  ][0] = r[0]; bfr[2*ng  ][1] = r[1];
                bfr[2*ng+1][0] = r[2]; bfr[2*ng+1][1] = r[3];
            }
            #pragma unroll
            for (int mt = 0; mt < 2; mt++)
                #pragma unroll
                for (int nt = 0; nt < NT; nt++)
                    mma16(acc[mt][nt], af[mt], bfr[nt]);
        }
        __syncthreads();
    }
    #undef QISSUE

    float* redm = reinterpret_cast<float*>(smp + AT_OFF_R);
    float* reds = redm + 256;

    float rmax[4] = {-3.4e38f, -3.4e38f, -3.4e38f, -3.4e38f};
    #pragma unroll
    for (int mt = 0; mt < 2; mt++){
        const int qi0 = row0 + mwb + mt*16 + g;
        const int qi1 = qi0 + 8;
        #pragma unroll
        for (int nt = 0; nt < NT; nt++){
            const int cx = nwb + nt*8 + c*2;
            float4 v = acc[mt][nt];
            v.x *= ATT_SCALE; v.y *= ATT_SCALE; v.z *= ATT_SCALE; v.w *= ATT_SCALE;
            int2 m0 = *reinterpret_cast<const int2*>(&mask[(size_t)qi0*TT + cx]);
            int2 m1 = *reinterpret_cast<const int2*>(&mask[(size_t)qi1*TT + cx]);
            bool okx = m0.x && (!causal || cx   <= qi0);
            bool oky = m0.y && (!causal || cx+1 <= qi0);
            bool okz = m1.x && (!causal || cx   <= qi1);
            bool okw = m1.y && (!causal || cx+1 <= qi1);
            v.x = okx ? v.x : NEGBIG;
            v.y = oky ? v.y : NEGBIG;
            v.z = okz ? v.z : NEGBIG;
            v.w = okw ? v.w : NEGBIG;
            acc[mt][nt] = v;
            rmax[mt*2+0] = fmaxf(rmax[mt*2+0], fmaxf(v.x, v.y));
            rmax[mt*2+1] = fmaxf(rmax[mt*2+1], fmaxf(v.z, v.w));
        }
    }
    #pragma unroll
    for (int h = 0; h < 4; h++){
        rmax[h] = fmaxf(rmax[h], __shfl_xor_sync(0xffffffffu, rmax[h], 1));
        rmax[h] = fmaxf(rmax[h], __shfl_xor_sync(0xffffffffu, rmax[h], 2));
    }
    const int half_ = w >> 2;
    if (c == 0){
        redm[half_*128 + mwb      + g] = rmax[0];
        redm[half_*128 + mwb +  8 + g] = rmax[1];
        redm[half_*128 + mwb + 16 + g] = rmax[2];
        redm[half_*128 + mwb + 24 + g] = rmax[3];
    }
    __syncthreads();
    float M[4];
    M[0] = fmaxf(redm[mwb      + g], redm[128 + mwb      + g]);
    M[1] = fmaxf(redm[mwb +  8 + g], redm[128 + mwb +  8 + g]);
    M[2] = fmaxf(redm[mwb + 16 + g], redm[128 + mwb + 16 + g]);
    M[3] = fmaxf(redm[mwb + 24 + g], redm[128 + mwb + 24 + g]);

    float rsum[4] = {0.f, 0.f, 0.f, 0.f};
    #pragma unroll
    for (int mt = 0; mt < 2; mt++){
        #pragma unroll
        for (int nt = 0; nt < NT; nt++){
            float4 v = acc[mt][nt];
            v.x = __expf(v.x - M[mt*2+0]);
            v.y = __expf(v.y - M[mt*2+0]);
            v.z = __expf(v.z - M[mt*2+1]);
            v.w = __expf(v.w - M[mt*2+1]);
            acc[mt][nt] = v;
            rsum[mt*2+0] += v.x + v.y;
            rsum[mt*2+1] += v.z + v.w;
        }
    }
    #pragma unroll
    for (int h = 0; h < 4; h++){
        rsum[h] += __shfl_xor_sync(0xffffffffu, rsum[h], 1);
        rsum[h] += __shfl_xor_sync(0xffffffffu, rsum[h], 2);
    }
    if (c == 0){
        reds[half_*128 + mwb      + g] = rsum[0];
        reds[half_*128 + mwb +  8 + g] = rsum[1];
        reds[half_*128 + mwb + 16 + g] = rsum[2];
        reds[half_*128 + mwb + 24 + g] = rsum[3];
    }
    __syncthreads();
    float inv[4];
    inv[0] = 1.f / (reds[mwb      + g] + reds[128 + mwb      + g]);
    inv[1] = 1.f / (reds[mwb +  8 + g] + reds[128 + mwb +  8 + g]);
    inv[2] = 1.f / (reds[mwb + 16 + g] + reds[128 + mwb + 16 + g]);
    inv[3] = 1.f / (reds[mwb + 24 + g] + reds[128 + mwb + 24 + g]);

    uint32_t pa[2][8][4];
    #pragma unroll
    for (int mt = 0; mt < 2; mt++){
        const float i0 = inv[mt*2+0], i1 = inv[mt*2+1];
        #pragma unroll
        for (int j = 0; j < 8; j++){
            float4 v0 = acc[mt][2*j], v1 = acc[mt][2*j+1];
            pa[mt][j][0] = h2pack(v0.x * i0, v0.y * i0);
            pa[mt][j][1] = h2pack(v0.z * i1, v0.w * i1);
            pa[mt][j][2] = h2pack(v1.x * i0, v1.y * i0);
            pa[mt][j][3] = h2pack(v1.z * i1, v1.w * i1);
        }
    }

    float4 accO[2][8];
    #pragma unroll
    for (int mt = 0; mt < 2; mt++)
        #pragma unroll
        for (int nt = 0; nt < 8; nt++)
            accO[mt][nt] = make_float4(0.f, 0.f, 0.f, 0.f);

    const int kb = ((lane>>3)&1)*8 + lrow;
    uint32_t vb[4];
    #pragma unroll
    for (int ng = 0; ng < 4; ng++){
        int nc = ng*2 + (lane>>4);
        vb[ng] = AT_OFF_V + (uint32_t)(nwb + kb)*128u + ((((uint32_t)nc ^ (uint32_t)(kb & 7)) & 7u) << 4);
    }
    #pragma unroll
    for (int j = 0; j < 8; j++){
        uint32_t bfr[8][2];
        #pragma unroll
        for (int ng = 0; ng < 4; ng++){
            uint32_t r[4];
            ldsm4t(r, smem_base + vb[ng] + (uint32_t)j*2048u);
            bfr[2*ng  ][0] = r[0]; bfr[2*ng  ][1] = r[1];
            bfr[2*ng+1][0] = r[2]; bfr[2*ng+1][1] = r[3];
        }
        #pragma unroll
        for (int mt = 0; mt < 2; mt++)
            #pragma unroll
            for (int nt = 0; nt < 8; nt++)
                mma16(accO[mt][nt], pa[mt][j], bfr[nt]);
    }

    float* ps = reinterpret_cast<float*>(smp);    // [128][66]
    if (half_ == 1){
        #pragma unroll
        for (int mt = 0; mt < 2; mt++){
            int rl = mwb + mt*16 + g;
            #pragma unroll
            for (int nt = 0; nt < 8; nt++){
                int cl = nt*8 + c*2;
                float4 v = accO[mt][nt];
                *reinterpret_cast<float2*>(&ps[(size_t)rl*66 + cl])     = make_float2(v.x, v.y);
                *reinterpret_cast<float2*>(&ps[(size_t)(rl+8)*66 + cl]) = make_float2(v.z, v.w);
            }
        }
    }
    __syncthreads();
    if (half_ == 0){
        #pragma unroll
        for (int mt = 0; mt < 2; mt++){
            int rl = mwb + mt*16 + g;
            #pragma unroll
            for (int nt = 0; nt < 8; nt++){
                int cl = nt*8 + c*2;
                float4 v = accO[mt][nt];
                float2 p0 = *reinterpret_cast<float2*>(&ps[(size_t)rl*66 + cl]);
                float2 p1 = *reinterpret_cast<float2*>(&ps[(size_t)(rl+8)*66 + cl]);
                *reinterpret_cast<__half2*>(&O[(size_t)(row0+rl)*CC + cl]) =
                    __floats2half2_rn(v.x + p0.x, v.y + p0.y);
                *reinterpret_cast<__half2*>(&O[(size_t)(row0+rl+8)*CC + cl]) =
                    __floats2half2_rn(v.z + p1.x, v.w + p1.y);
            }
        }
    }
}

// ---------------- host orchestration ----------------
template<typename T>
static T* symaddr(const void* sym){
    void* p = nullptr;
    cudaGetSymbolAddress(&p, sym);
    return (T*)p;
}

#define S3H128 (3*(128*128 + 128*128))   // 98304
#define S3H64  (3*(128*128 + 64*128))    // 73728

#define G_PROJ gemm_h<128,false,false,false,true >
#define G_FF1  gemm_h<128,true ,true ,false,true >
#define G_WO64 gemm_h<64 ,true ,false,true ,false>
#define G_QC64 gemm_h<64 ,false,false,false,true >

extern "C" void kernel_launch(void* const* d_in, const int* in_sizes, int n_in,
                              void* d_out, int out_size)
{
    const float* x    = (const float*)d_in[0];
    const float* ca   = (const float*)d_in[1];
    const int*   x_m  = (const int*)  d_in[2];
    const int*   ca_m = (const int*)  d_in[3];
    const float* Wq_s = (const float*)d_in[4];
    const float* Wk_s = (const float*)d_in[5];
    const float* Wv_s = (const float*)d_in[6];
    const float* Wo_s = (const float*)d_in[7];
    const float* bo_s = (const float*)d_in[8];
    const float* Wq_c = (const float*)d_in[9];
    const float* Wk_c = (const float*)d_in[10];
    const float* Wv_c = (const float*)d_in[11];
    const float* Wo_c = (const float*)d_in[12];
    const float* bo_c = (const float*)d_in[13];
    const float* g1   = (const float*)d_in[14];
    const float* be1  = (const float*)d_in[15];
    const float* g2   = (const float*)d_in[16];
    const float* be2  = (const float*)d_in[17];
    const float* g3   = (const float*)d_in[18];
    const float* be3  = (const float*)d_in[19];
    const float* Wf1  = (const float*)d_in[20];
    const float* bf1  = (const float*)d_in[21];
    const float* Wf2  = (const float*)d_in[22];
    const float* bf2  = (const float*)d_in[23];
    float* out = (float*)d_out;

    __half* p_ln  = symaddr<__half>(g_ln);
    __half* p_qkv = symaddr<__half>(g_qkv);
    __half* p_qc  = symaddr<__half>(g_qc);
    __half* p_kvc = symaddr<__half>(g_kvc);
    __half* p_att = symaddr<__half>(g_att);
    __half* p_ca  = symaddr<__half>(g_ca);
    __half* p_h   = symaddr<__half>(g_h);
    __half* p_wqs = symaddr<__half>(g_wqkvs);
    __half* p_wqc = symaddr<__half>(g_wqkvc);
    __half* p_wos = symaddr<__half>(g_wos);
    __half* p_woc = symaddr<__half>(g_woc);
    __half* p_wf1 = symaddr<__half>(g_wf1t);
    __half* p_wf2 = symaddr<__half>(g_wf2t);
    float*  p_x1  = symaddr<float>(g_x1);
    float*  p_x2  = symaddr<float>(g_x2);

    static cudaStream_t s1 = nullptr;
    static cudaEvent_t evRoot = nullptr, evW = nullptr, evW2 = nullptr, evKV = nullptr;
    static bool initDone = false;
    if (!initDone){
        cudaFuncSetAttribute(G_PROJ, cudaFuncAttributeMaxDynamicSharedMemorySize, S3H128);
        cudaFuncSetAttribute(G_FF1,  cudaFuncAttributeMaxDynamicSharedMemorySize, S3H128);
        cudaFuncSetAttribute(G_WO64, cudaFuncAttributeMaxDynamicSharedMemorySize, S3H64);
        cudaFuncSetAttribute(G_QC64, cudaFuncAttributeMaxDynamicSharedMemorySize, S3H64);
        cudaFuncSetAttribute(attn,   cudaFuncAttributeMaxDynamicSharedMemorySize, AT_SMEM);
        cudaStreamCreateWithFlags(&s1, cudaStreamNonBlocking);
        cudaEventCreateWithFlags(&evRoot, cudaEventDisableTiming);
        cudaEventCreateWithFlags(&evW,    cudaEventDisableTiming);
        cudaEventCreateWithFlags(&evW2,   cudaEventDisableTiming);
        cudaEventCreateWithFlags(&evKV,   cudaEventDisableTiming);
        initDone = true;
    }

    dim3 tb(32, 8);
    dim3 gQKV (QKV/128, MROWS/128, 1);    // (12,128)
    dim3 gKVc (1024/128,MROWS/128, 1);    // (8,128)
    dim3 gCC64(CC/64,  MROWS/128, 1);     // (8,128) = 1024 CTAs
    dim3 gFF  (FF/128, MROWS/128, 1);     // (16,128)
    dim3 gAT  (TT/128, BATCH*NHD);

    // ===== fork side stream: prepass + cross K/V projection =====
    cudaEventRecord(evRoot, 0);
    cudaStreamWaitEvent(s1, evRoot, 0);
    wtrans8<<<dim3(16,16,8), tb, 0, s1>>>(Wq_s, Wk_s, Wv_s, Wo_s, Wq_c, Wk_c, Wv_c, Wo_c,
                                          p_wqs, p_wos, p_wqc, p_woc);
    cudaEventRecord(evW, s1);
    f2h_kernel<<<(MROWS*CC/4+255)/256, 256, 0, s1>>>(ca, p_ca, MROWS*CC/4);
    G_PROJ<<<gKVc,256,S3H128,s1>>>(p_ca, CC, p_wqc + (size_t)CC*CC, CC, nullptr, nullptr,
                                   p_kvc, 1024, CC);
    cudaEventRecord(evKV, s1);
    ttrans<<<dim3(FF/32, CC/32), tb, 0, s1>>>(Wf1, p_wf1, CC, FF);
    ttrans<<<dim3(CC/32, FF/32), tb, 0, s1>>>(Wf2, p_wf2, FF, CC);
    cudaEventRecord(evW2, s1);

    // ===== main chain (default stream) =====
    // self-attention
    ln_kernel<<<MROWS,128>>>(x, g1, be1, p_ln);
    cudaStreamWaitEvent(0, evW, 0);
    G_PROJ<<<gQKV,256,S3H128>>>(p_ln, CC, p_wqs, CC, nullptr, nullptr, p_qkv, QKV, CC);
    attn<<<gAT,256,AT_SMEM>>>(p_qkv, QKV, p_qkv + CC, p_qkv + 1024, QKV, x_m, p_att, 1);
    G_WO64<<<gCC64,256,S3H64>>>(p_att, CC, p_wos, CC, bo_s, x, p_x1, CC, CC);

    // cross-attention
    ln_kernel<<<MROWS,128>>>(p_x1, g2, be2, p_ln);
    G_QC64<<<gCC64,256,S3H64>>>(p_ln, CC, p_wqc, CC, nullptr, nullptr, p_qc, CC, CC);
    cudaStreamWaitEvent(0, evKV, 0);
    attn<<<gAT,256,AT_SMEM>>>(p_qc, CC, p_kvc, p_kvc + CC, 1024, ca_m, p_att, 0);
    G_WO64<<<gCC64,256,S3H64>>>(p_att, CC, p_woc, CC, bo_c, p_x1, p_x2, CC, CC);

    // feed-forward
    ln_kernel<<<MROWS,128>>>(p_x2, g3, be3, p_ln);
    cudaStreamWaitEvent(0, evW2, 0);
    G_FF1<<<gFF,256,S3H128>>>(p_ln, CC, p_wf1, CC, bf1, nullptr, p_h, FF, CC);
    G_WO64<<<gCC64,256,S3H64>>>(p_h, FF, p_wf2, FF, bf2, p_x2, out, CC, FF);

    (void)in_sizes; (void)n_in; (void)out_size;
}

// round 15
// speedup vs baseline: 1.0223x; 1.0223x over previous
#include <cuda_runtime.h>
#include <cuda_fp16.h>
#include <cstdint>

#define BATCH 64
#define TT 256
#define CC 512
#define NHD 8
#define HD 64
#define MROWS (BATCH*TT)      // 16384
#define FF 2048
#define QKV 1536
#define ATT_SCALE 0.044194173824159216f   // 512^-0.5
#define NEGBIG (-1e9f)

// ---------------- scratch (device globals; no allocations) ----------------
__device__ __half g_ln  [MROWS*CC];
__device__ __half g_qkv [(size_t)MROWS*QKV];
__device__ __half g_qc  [MROWS*CC];                  // cross-attn Q
__device__ __half g_kvc [(size_t)MROWS*1024];        // cross-attn K|V
__device__ __half g_att [MROWS*CC];
__device__ __half g_ca  [MROWS*CC];
__device__ __half g_h   [(size_t)MROWS*FF];
__device__ __half g_wqkvs[QKV*CC];
__device__ __half g_wqkvc[QKV*CC];
__device__ __half g_wos [CC*CC];
__device__ __half g_woc [CC*CC];
__device__ __half g_wf1t[FF*CC];
__device__ __half g_wf2t[CC*FF];
__device__ float  g_x1  [MROWS*CC];
__device__ float  g_x2  [MROWS*CC];

// ---------------- helpers ----------------
__device__ __forceinline__ void mma16(float4& d, const uint32_t* a, const uint32_t* b){
    asm volatile("mma.sync.aligned.m16n8k16.row.col.f32.f16.f16.f32 "
        "{%0,%1,%2,%3}, {%4,%5,%6,%7}, {%8,%9}, {%0,%1,%2,%3};"
        : "+f"(d.x), "+f"(d.y), "+f"(d.z), "+f"(d.w)
        : "r"(a[0]), "r"(a[1]), "r"(a[2]), "r"(a[3]), "r"(b[0]), "r"(b[1]));
}
__device__ __forceinline__ void ldsm4(uint32_t* r, uint32_t addr){
    asm volatile("ldmatrix.sync.aligned.m8n8.x4.shared.b16 {%0,%1,%2,%3}, [%4];"
        : "=r"(r[0]), "=r"(r[1]), "=r"(r[2]), "=r"(r[3]) : "r"(addr));
}
__device__ __forceinline__ void ldsm4t(uint32_t* r, uint32_t addr){
    asm volatile("ldmatrix.sync.aligned.m8n8.x4.trans.shared.b16 {%0,%1,%2,%3}, [%4];"
        : "=r"(r[0]), "=r"(r[1]), "=r"(r[2]), "=r"(r[3]) : "r"(addr));
}
__device__ __forceinline__ uint32_t h2pack(float a, float b){
    __half2 h = __floats2half2_rn(a, b);
    return *reinterpret_cast<uint32_t*>(&h);
}
#define CP16(d, s) asm volatile("cp.async.cg.shared.global [%0], [%1], 16;" :: "r"(d), "l"(s))
#define CPCOMMIT() asm volatile("cp.async.commit_group;" ::: "memory")
#define CPWAIT(n)  asm volatile("cp.async.wait_group %0;" :: "n"(n) : "memory")

__device__ __forceinline__ float warpSum(float v){
    #pragma unroll
    for (int o = 16; o; o >>= 1) v += __shfl_xor_sync(0xffffffffu, v, o);
    return v;
}

// ---------------- prepass: weight transpose -> fp16 [N][K] ----------------
__global__ void wtrans8(const float* s0, const float* s1, const float* s2, const float* s3,
                        const float* s4, const float* s5, const float* s6, const float* s7,
                        __half* qkvs, __half* wos, __half* qkvc, __half* woc)
{
    int z = blockIdx.z;
    const float* src = (z==0)?s0:(z==1)?s1:(z==2)?s2:(z==3)?s3:(z==4)?s4:(z==5)?s5:(z==6)?s6:s7;
    __half* dst = (z<3) ? qkvs + (size_t)z*CC*CC
               : (z==3) ? wos
               : (z<7) ? qkvc + (size_t)(z-4)*CC*CC
               : woc;
    __shared__ float t[32][33];
    int bx = blockIdx.x*32, by = blockIdx.y*32;
    int x = threadIdx.x, y = threadIdx.y;
    #pragma unroll
    for (int i = 0; i < 32; i += 8)
        t[y+i][x] = src[(size_t)(by + y + i)*CC + bx + x];
    __syncthreads();
    #pragma unroll
    for (int i = 0; i < 32; i += 8)
        dst[(size_t)(bx + y + i)*CC + by + x] = __float2half_rn(t[x][y+i]);
}

__global__ void ttrans(const float* __restrict__ src, __half* __restrict__ dst, int R, int C)
{
    __shared__ float t[32][33];
    int bx = blockIdx.x*32, by = blockIdx.y*32;
    int x = threadIdx.x, y = threadIdx.y;
    #pragma unroll
    for (int i = 0; i < 32; i += 8)
        t[y+i][x] = src[(size_t)(by + y + i)*C + bx + x];
    __syncthreads();
    #pragma unroll
    for (int i = 0; i < 32; i += 8)
        dst[(size_t)(bx + y + i)*R + by + x] = __float2half_rn(t[x][y+i]);
}

__global__ void f2h_kernel(const float* __restrict__ src, __half* __restrict__ dst, int n4){
    int i = blockIdx.x*256 + threadIdx.x;
    if (i < n4){
        float4 v = reinterpret_cast<const float4*>(src)[i];
        reinterpret_cast<__half2*>(dst)[2*i]   = __floats2half2_rn(v.x, v.y);
        reinterpret_cast<__half2*>(dst)[2*i+1] = __floats2half2_rn(v.z, v.w);
    }
}

// ---------------- layernorm: one WARP per row (no smem, no block sync) ----------------
__global__ __launch_bounds__(256)
void ln_kernel(const float* __restrict__ x, const float* __restrict__ g,
               const float* __restrict__ be, __half* __restrict__ y)
{
    const int r    = blockIdx.x*8 + (threadIdx.x >> 5);
    const int lane = threadIdx.x & 31;
    const float4* xr = reinterpret_cast<const float4*>(x + (size_t)r*CC);

    float4 v[4];
    float s = 0.f, sq = 0.f;
    #pragma unroll
    for (int i = 0; i < 4; i++){
        v[i] = xr[lane + 32*i];
        s  += v[i].x + v[i].y + v[i].z + v[i].w;
        sq += v[i].x*v[i].x + v[i].y*v[i].y + v[i].z*v[i].z + v[i].w*v[i].w;
    }
    s  = warpSum(s);
    sq = warpSum(sq);
    const float mu   = s * (1.0f/CC);
    const float var  = sq * (1.0f/CC) - mu*mu;
    const float rstd = rsqrtf(var + 1e-5f);

    const float4* g4  = reinterpret_cast<const float4*>(g);
    const float4* be4 = reinterpret_cast<const float4*>(be);
    __half2* yh = reinterpret_cast<__half2*>(y + (size_t)r*CC);
    #pragma unroll
    for (int i = 0; i < 4; i++){
        float4 gg = g4[lane + 32*i], bb = be4[lane + 32*i];
        yh[2*(lane + 32*i)]     = __floats2half2_rn((v[i].x - mu)*rstd*gg.x + bb.x,
                                                    (v[i].y - mu)*rstd*gg.y + bb.y);
        yh[2*(lane + 32*i) + 1] = __floats2half2_rn((v[i].z - mu)*rstd*gg.z + bb.z,
                                                    (v[i].w - mu)*rstd*gg.w + bb.w);
    }
}

// =================== fp16 mma.sync GEMM: BK=64, B [N][K], BN=128 ===================
// Single barrier per chunk: CPWAIT -> syncthreads -> ISSUE(ch+2) -> mma.
template<bool BIAS, bool RELU, bool RES, bool HOUT>
__global__ __launch_bounds__(256, 2)
void gemm_h(const __half* __restrict__ A, int lda,
            const __half* __restrict__ B, int ldb,
            const float* __restrict__ bias, const float* __restrict__ res,
            void* __restrict__ Cv, int ldc, int K)
{
    constexpr int NT = 8;
    constexpr int ABYTES = 128*128;
    constexpr int STAGE  = 2*ABYTES;

    extern __shared__ char smp[];
    const uint32_t smem_base = (uint32_t)__cvta_generic_to_shared(smp);

    const int tid  = threadIdx.x;
    const int w    = tid >> 5, lane = tid & 31;
    const int g    = lane >> 2, c = lane & 3;
    const int row0 = blockIdx.y * 128;
    const int col0 = blockIdx.x * 128;

    float* Cf = (float*)Cv;
    __half* Ch = (__half*)Cv;

    float4 acc[2][NT];
    #pragma unroll
    for (int mt = 0; mt < 2; mt++)
        #pragma unroll
        for (int nt = 0; nt < NT; nt++)
            acc[mt][nt] = make_float4(0.f, 0.f, 0.f, 0.f);

    const int nch = K >> 6;
    const int mwb = (w & 3) * 32;
    const int nwb = (w >> 2) * 64;

    const int lrow = lane & 7;
    uint32_t aBase[2], aSw[2];
    const uint32_t aKc = (uint32_t)(lane >> 4);
    #pragma unroll
    for (int mt = 0; mt < 2; mt++){
        int m = mwb + mt*16 + ((lane>>3)&1)*8 + lrow;
        aBase[mt] = (uint32_t)m * 128u;
        aSw[mt]   = (uint32_t)(m & 7);
    }
    uint32_t bBase[NT/2], bSw[NT/2];
    const uint32_t bKc = (uint32_t)((lane>>3)&1);
    #pragma unroll
    for (int ng = 0; ng < NT/2; ng++){
        int n = nwb + ng*16 + (lane>>4)*8 + lrow;
        bBase[ng] = (uint32_t)n * 128u;
        bSw[ng]   = (uint32_t)(n & 7);
    }

    #define ISSUE(ch, s) do { \
        const uint32_t sa = smem_base + (s)*STAGE; \
        const __half* Ag = A + (size_t)row0*lda + (ch)*64; \
        _Pragma("unroll") \
        for (int i = 0; i < 4; i++){ \
            int t2 = tid + 256*i; int m = t2 >> 3, c2 = t2 & 7; \
            CP16(sa + m*128 + ((c2 ^ (m & 7)) << 4), Ag + (size_t)m*lda + c2*8); \
        } \
        const uint32_t sb2 = sa + ABYTES; \
        const __half* Bg = B + (size_t)col0*ldb + (ch)*64; \
        _Pragma("unroll") \
        for (int i = 0; i < 4; i++){ \
            int t2 = tid + 256*i; int n = t2 >> 3, c2 = t2 & 7; \
            CP16(sb2 + n*128 + ((c2 ^ (n & 7)) << 4), Bg + (size_t)n*ldb + c2*8); \
        } \
        CPCOMMIT(); \
    } while(0)

    ISSUE(0, 0);
    ISSUE(1, 1);

    for (int ch = 0; ch < nch; ch++){
        const int p = ch % 3;
        if (ch == nch - 1) CPWAIT(0); else CPWAIT(1);
        __syncthreads();
        if (ch + 2 < nch) ISSUE(ch+2, (ch+2)%3);

        const uint32_t sA = smem_base + p*STAGE;
        const uint32_t sB = sA + ABYTES;

        #pragma unroll
        for (int ks = 0; ks < 4; ks++){
            uint32_t af[2][4], bfr[NT][2];
            #pragma unroll
            for (int mt = 0; mt < 2; mt++)
                ldsm4(af[mt], sA + aBase[mt] + ((((uint32_t)(2*ks) + aKc) ^ aSw[mt]) << 4));
            #pragma unroll
            for (int ng = 0; ng < NT/2; ng++){
                uint32_t r[4];
                ldsm4(r, sB + bBase[ng] + ((((uint32_t)(2*ks) + bKc) ^ bSw[ng]) << 4));
                bfr[2*ng  ][0] = r[0]; bfr[2*ng  ][1] = r[1];
                bfr[2*ng+1][0] = r[2]; bfr[2*ng+1][1] = r[3];
            }
            #pragma unroll
            for (int mt = 0; mt < 2; mt++)
                #pragma unroll
                for (int nt = 0; nt < NT; nt++)
                    mma16(acc[mt][nt], af[mt], bfr[nt]);
        }
    }

    #pragma unroll
    for (int mt = 0; mt < 2; mt++){
        int r0 = row0 + mwb + mt*16 + g;
        #pragma unroll
        for (int nt = 0; nt < NT; nt++){
            int cx = col0 + nwb + nt*8 + c*2;
            float4 v = acc[mt][nt];
            if (BIAS){
                float b0 = bias[cx], b1 = bias[cx+1];
                v.x += b0; v.y += b1; v.z += b0; v.w += b1;
            }
            if (RELU){
                v.x = fmaxf(v.x, 0.f); v.y = fmaxf(v.y, 0.f);
                v.z = fmaxf(v.z, 0.f); v.w = fmaxf(v.w, 0.f);
            }
            if (RES){
                float2 r1 = *reinterpret_cast<const float2*>(&res[(size_t)r0*ldc + cx]);
                float2 r2 = *reinterpret_cast<const float2*>(&res[(size_t)(r0+8)*ldc + cx]);
                v.x += r1.x; v.y += r1.y; v.z += r2.x; v.w += r2.y;
            }
            if (HOUT){
                *reinterpret_cast<__half2*>(&Ch[(size_t)r0*ldc + cx])     = __floats2half2_rn(v.x, v.y);
                *reinterpret_cast<__half2*>(&Ch[(size_t)(r0+8)*ldc + cx]) = __floats2half2_rn(v.z, v.w);
            } else {
                *reinterpret_cast<float2*>(&Cf[(size_t)r0*ldc + cx])     = make_float2(v.x, v.y);
                *reinterpret_cast<float2*>(&Cf[(size_t)(r0+8)*ldc + cx]) = make_float2(v.z, v.w);
            }
        }
    }
    #undef ISSUE
}

// =================== fused attention: QK^T + mask + softmax + P@V ===================
#define AT_STAGE (128*64 + 256*64)
#define AT_OFF_V (2*AT_STAGE)
#define AT_OFF_R (AT_OFF_V + 256*128)
#define AT_SMEM  (AT_OFF_R + 2048)
__global__ __launch_bounds__(256, 1)
void attn(const __half* __restrict__ Q, int ldq,
          const __half* __restrict__ Kmat, const __half* __restrict__ V, int ldkv,
          const int* __restrict__ mask, __half* __restrict__ O, int causal)
{
    constexpr int NT = 16;
    extern __shared__ char smp[];
    const uint32_t smem_base = (uint32_t)__cvta_generic_to_shared(smp);

    const int tid  = threadIdx.x;
    const int w    = tid >> 5, lane = tid & 31;
    const int g    = lane >> 2, c = lane & 3;
    const int row0 = blockIdx.x * 128;
    {
        const long long zb = blockIdx.y >> 3, zh = blockIdx.y & 7;
        Q    += zb*(long long)TT*ldq  + zh*HD;
        Kmat += zb*(long long)TT*ldkv + zh*HD;
        V    += zb*(long long)TT*ldkv + zh*HD;
        mask += zb*(long long)TT*TT;
        O    += zb*(long long)TT*CC + zh*HD;
    }

    float4 acc[2][NT];
    #pragma unroll
    for (int mt = 0; mt < 2; mt++)
        #pragma unroll
        for (int nt = 0; nt < NT; nt++)
            acc[mt][nt] = make_float4(0.f, 0.f, 0.f, 0.f);

    const int mwb = (w & 3) * 32;
    const int nwb = (w >> 2) * 128;

    const int lrow = lane & 7;
    uint32_t aBase[2], aSw[2];
    const uint32_t aKc = (uint32_t)(lane >> 4);
    #pragma unroll
    for (int mt = 0; mt < 2; mt++){
        int m = mwb + mt*16 + ((lane>>3)&1)*8 + lrow;
        aBase[mt] = (uint32_t)m * 64u;
        aSw[mt]   = (uint32_t)((m>>1)&3);
    }
    uint32_t bBase[8], bSw[8];
    const uint32_t bKc = (uint32_t)((lane>>3)&1);
    #pragma unroll
    for (int ng = 0; ng < 8; ng++){
        int n = nwb + ng*16 + (lane>>4)*8 + lrow;
        bBase[ng] = (uint32_t)n * 64u;
        bSw[ng]   = (uint32_t)((n>>1)&3);
    }

    #define QISSUE(ch, s) do { \
        const uint32_t sa = smem_base + (s)*AT_STAGE; \
        const __half* Ag = Q + (size_t)row0*ldq + (ch)*32; \
        _Pragma("unroll") \
        for (int i = 0; i < 2; i++){ \
            int t2 = tid + 256*i; int m = t2 >> 2, c2 = t2 & 3; \
            CP16(sa + m*64 + ((c2 ^ ((m>>1)&3)) << 4), Ag + (size_t)m*ldq + c2*8); \
        } \
        const uint32_t sb2 = sa + 128*64; \
        const __half* Bg = Kmat + (ch)*32; \
        _Pragma("unroll") \
        for (int i = 0; i < 4; i++){ \
            int t2 = tid + 256*i; int n = t2 >> 2, c2 = t2 & 3; \
            CP16(sb2 + n*64 + ((c2 ^ ((n>>1)&3)) << 4), Bg + (size_t)n*ldkv + c2*8); \
        } \
        CPCOMMIT(); \
    } while(0)

    QISSUE(0, 0);
    {
        #pragma unroll
        for (int i = 0; i < 8; i++){
            int idx = tid + 256*i;
            int t2 = idx >> 3, c2 = idx & 7;
            CP16(smem_base + AT_OFF_V + t2*128 + ((c2 ^ (t2 & 7)) << 4),
                 V + (size_t)t2*ldkv + c2*8);
        }
        CPCOMMIT();
    }
    QISSUE(1, 1);

    #pragma unroll
    for (int ch = 0; ch < 2; ch++){
        if (ch == 0) CPWAIT(2); else CPWAIT(0);
        __syncthreads();
        const uint32_t sA = smem_base + ch*AT_STAGE;
        const uint32_t sB = sA + 128*64;
        #pragma unroll
        for (int ks = 0; ks < 2; ks++){
            uint32_t af[2][4], bfr[NT][2];
            #pragma unroll
            for (int mt = 0; mt < 2; mt++)
                ldsm4(af[mt], sA + aBase[mt] + ((((uint32_t)(2*ks) + aKc) ^ aSw[mt]) << 4));
            #pragma unroll
            for (int ng = 0; ng < 8; ng++){
                uint32_t r[4];
                ldsm4(r, sB + bBase[ng] + ((((uint32_t)(2*ks) + bKc) ^ bSw[ng]) << 4));
                bfr[2*ng  ][0] = r[0]; bfr[2*ng  ][1] = r[1];
                bfr[2*ng+1][0] = r[2]; bfr[2*ng+1][1] = r[3];
            }
            #pragma unroll
            for (int mt = 0; mt < 2; mt++)
                #pragma unroll
                for (int nt = 0; nt < NT; nt++)
                    mma16(acc[mt][nt], af[mt], bfr[nt]);
        }
        __syncthreads();
    }
    #undef QISSUE

    float* redm = reinterpret_cast<float*>(smp + AT_OFF_R);
    float* reds = redm + 256;

    float rmax[4] = {-3.4e38f, -3.4e38f, -3.4e38f, -3.4e38f};
    #pragma unroll
    for (int mt = 0; mt < 2; mt++){
        const int qi0 = row0 + mwb + mt*16 + g;
        const int qi1 = qi0 + 8;
        #pragma unroll
        for (int nt = 0; nt < NT; nt++){
            const int cx = nwb + nt*8 + c*2;
            float4 v = acc[mt][nt];
            v.x *= ATT_SCALE; v.y *= ATT_SCALE; v.z *= ATT_SCALE; v.w *= ATT_SCALE;
            int2 m0 = *reinterpret_cast<const int2*>(&mask[(size_t)qi0*TT + cx]);
            int2 m1 = *reinterpret_cast<const int2*>(&mask[(size_t)qi1*TT + cx]);
            bool okx = m0.x && (!causal || cx   <= qi0);
            bool oky = m0.y && (!causal || cx+1 <= qi0);
            bool okz = m1.x && (!causal || cx   <= qi1);
            bool okw = m1.y && (!causal || cx+1 <= qi1);
            v.x = okx ? v.x : NEGBIG;
            v.y = oky ? v.y : NEGBIG;
            v.z = okz ? v.z : NEGBIG;
            v.w = okw ? v.w : NEGBIG;
            acc[mt][nt] = v;
            rmax[mt*2+0] = fmaxf(rmax[mt*2+0], fmaxf(v.x, v.y));
            rmax[mt*2+1] = fmaxf(rmax[mt*2+1], fmaxf(v.z, v.w));
        }
    }
    #pragma unroll
    for (int h = 0; h < 4; h++){
        rmax[h] = fmaxf(rmax[h], __shfl_xor_sync(0xffffffffu, rmax[h], 1));
        rmax[h] = fmaxf(rmax[h], __shfl_xor_sync(0xffffffffu, rmax[h], 2));
    }
    const int half_ = w >> 2;
    if (c == 0){
        redm[half_*128 + mwb      + g] = rmax[0];
        redm[half_*128 + mwb +  8 + g] = rmax[1];
        redm[half_*128 + mwb + 16 + g] = rmax[2];
        redm[half_*128 + mwb + 24 + g] = rmax[3];
    }
    __syncthreads();
    float M[4];
    M[0] = fmaxf(redm[mwb      + g], redm[128 + mwb      + g]);
    M[1] = fmaxf(redm[mwb +  8 + g], redm[128 + mwb +  8 + g]);
    M[2] = fmaxf(redm[mwb + 16 + g], redm[128 + mwb + 16 + g]);
    M[3] = fmaxf(redm[mwb + 24 + g], redm[128 + mwb + 24 + g]);

    float rsum[4] = {0.f, 0.f, 0.f, 0.f};
    #pragma unroll
    for (int mt = 0; mt < 2; mt++){
        #pragma unroll
        for (int nt = 0; nt < NT; nt++){
            float4 v = acc[mt][nt];
            v.x = __expf(v.x - M[mt*2+0]);
            v.y = __expf(v.y - M[mt*2+0]);
            v.z = __expf(v.z - M[mt*2+1]);
            v.w = __expf(v.w - M[mt*2+1]);
            acc[mt][nt] = v;
            rsum[mt*2+0] += v.x + v.y;
            rsum[mt*2+1] += v.z + v.w;
        }
    }
    #pragma unroll
    for (int h = 0; h < 4; h++){
        rsum[h] += __shfl_xor_sync(0xffffffffu, rsum[h], 1);
        rsum[h] += __shfl_xor_sync(0xffffffffu, rsum[h], 2);
    }
    if (c == 0){
        reds[half_*128 + mwb      + g] = rsum[0];
        reds[half_*128 + mwb +  8 + g] = rsum[1];
        reds[half_*128 + mwb + 16 + g] = rsum[2];
        reds[half_*128 + mwb + 24 + g] = rsum[3];
    }
    __syncthreads();
    float inv[4];
    inv[0] = 1.f / (reds[mwb      + g] + reds[128 + mwb      + g]);
    inv[1] = 1.f / (reds[mwb +  8 + g] + reds[128 + mwb +  8 + g]);
    inv[2] = 1.f / (reds[mwb + 16 + g] + reds[128 + mwb + 16 + g]);
    inv[3] = 1.f / (reds[mwb + 24 + g] + reds[128 + mwb + 24 + g]);

    uint32_t pa[2][8][4];
    #pragma unroll
    for (int mt = 0; mt < 2; mt++){
        const float i0 = inv[mt*2+0], i1 = inv[mt*2+1];
        #pragma unroll
        for (int j = 0; j < 8; j++){
            float4 v0 = acc[mt][2*j], v1 = acc[mt][2*j+1];
            pa[mt][j][0] = h2pack(v0.x * i0, v0.y * i0);
            pa[mt][j][1] = h2pack(v0.z * i1, v0.w * i1);
            pa[mt][j][2] = h2pack(v1.x * i0, v1.y * i0);
            pa[mt][j][3] = h2pack(v1.z * i1, v1.w * i1);
        }
    }

    float4 accO[2][8];
    #pragma unroll
    for (int mt = 0; mt < 2; mt++)
        #pragma unroll
        for (int nt = 0; nt < 8; nt++)
            accO[mt][nt] = make_float4(0.f, 0.f, 0.f, 0.f);

    const int kb = ((lane>>3)&1)*8 + lrow;
    uint32_t vb[4];
    #pragma unroll
    for (int ng = 0; ng < 4; ng++){
        int nc = ng*2 + (lane>>4);
        vb[ng] = AT_OFF_V + (uint32_t)(nwb + kb)*128u + ((((uint32_t)nc ^ (uint32_t)(kb & 7)) & 7u) << 4);
    }
    #pragma unroll
    for (int j = 0; j < 8; j++){
        uint32_t bfr[8][2];
        #pragma unroll
        for (int ng = 0; ng < 4; ng++){
            uint32_t r[4];
            ldsm4t(r, smem_base + vb[ng] + (uint32_t)j*2048u);
            bfr[2*ng  ][0] = r[0]; bfr[2*ng  ][1] = r[1];
            bfr[2*ng+1][0] = r[2]; bfr[2*ng+1][1] = r[3];
        }
        #pragma unroll
        for (int mt = 0; mt < 2; mt++)
            #pragma unroll
            for (int nt = 0; nt < 8; nt++)
                mma16(accO[mt][nt], pa[mt][j], bfr[nt]);
    }

    float* ps = reinterpret_cast<float*>(smp);    // [128][66]
    if (half_ == 1){
        #pragma unroll
        for (int mt = 0; mt < 2; mt++){
            int rl = mwb + mt*16 + g;
            #pragma unroll
            for (int nt = 0; nt < 8; nt++){
                int cl = nt*8 + c*2;
                float4 v = accO[mt][nt];
                *reinterpret_cast<float2*>(&ps[(size_t)rl*66 + cl])     = make_float2(v.x, v.y);
                *reinterpret_cast<float2*>(&ps[(size_t)(rl+8)*66 + cl]) = make_float2(v.z, v.w);
            }
        }
    }
    __syncthreads();
    if (half_ == 0){
        #pragma unroll
        for (int mt = 0; mt < 2; mt++){
            int rl = mwb + mt*16 + g;
            #pragma unroll
            for (int nt = 0; nt < 8; nt++){
                int cl = nt*8 + c*2;
                float4 v = accO[mt][nt];
                float2 p0 = *reinterpret_cast<float2*>(&ps[(size_t)rl*66 + cl]);
                float2 p1 = *reinterpret_cast<float2*>(&ps[(size_t)(rl+8)*66 + cl]);
                *reinterpret_cast<__half2*>(&O[(size_t)(row0+rl)*CC + cl]) =
                    __floats2half2_rn(v.x + p0.x, v.y + p0.y);
                *reinterpret_cast<__half2*>(&O[(size_t)(row0+rl+8)*CC + cl]) =
                    __floats2half2_rn(v.z + p1.x, v.w + p1.y);
            }
        }
    }
}

// ---------------- host orchestration ----------------
template<typename T>
static T* symaddr(const void* sym){
    void* p = nullptr;
    cudaGetSymbolAddress(&p, sym);
    return (T*)p;
}

#define S3H  (3*(128*128 + 128*128))   // 98304

#define G_PROJ gemm_h<false,false,false,true >
#define G_WO   gemm_h<true ,false,true ,false>
#define G_FF1  gemm_h<true ,true ,false,true >

extern "C" void kernel_launch(void* const* d_in, const int* in_sizes, int n_in,
                              void* d_out, int out_size)
{
    const float* x    = (const float*)d_in[0];
    const float* ca   = (const float*)d_in[1];
    const int*   x_m  = (const int*)  d_in[2];
    const int*   ca_m = (const int*)  d_in[3];
    const float* Wq_s = (const float*)d_in[4];
    const float* Wk_s = (const float*)d_in[5];
    const float* Wv_s = (const float*)d_in[6];
    const float* Wo_s = (const float*)d_in[7];
    const float* bo_s = (const float*)d_in[8];
    const float* Wq_c = (const float*)d_in[9];
    const float* Wk_c = (const float*)d_in[10];
    const float* Wv_c = (const float*)d_in[11];
    const float* Wo_c = (const float*)d_in[12];
    const float* bo_c = (const float*)d_in[13];
    const float* g1   = (const float*)d_in[14];
    const float* be1  = (const float*)d_in[15];
    const float* g2   = (const float*)d_in[16];
    const float* be2  = (const float*)d_in[17];
    const float* g3   = (const float*)d_in[18];
    const float* be3  = (const float*)d_in[19];
    const float* Wf1  = (const float*)d_in[20];
    const float* bf1  = (const float*)d_in[21];
    const float* Wf2  = (const float*)d_in[22];
    const float* bf2  = (const float*)d_in[23];
    float* out = (float*)d_out;

    __half* p_ln  = symaddr<__half>(g_ln);
    __half* p_qkv = symaddr<__half>(g_qkv);
    __half* p_qc  = symaddr<__half>(g_qc);
    __half* p_kvc = symaddr<__half>(g_kvc);
    __half* p_att = symaddr<__half>(g_att);
    __half* p_ca  = symaddr<__half>(g_ca);
    __half* p_h   = symaddr<__half>(g_h);
    __half* p_wqs = symaddr<__half>(g_wqkvs);
    __half* p_wqc = symaddr<__half>(g_wqkvc);
    __half* p_wos = symaddr<__half>(g_wos);
    __half* p_woc = symaddr<__half>(g_woc);
    __half* p_wf1 = symaddr<__half>(g_wf1t);
    __half* p_wf2 = symaddr<__half>(g_wf2t);
    float*  p_x1  = symaddr<float>(g_x1);
    float*  p_x2  = symaddr<float>(g_x2);

    static cudaStream_t s1 = nullptr;
    static cudaEvent_t evRoot = nullptr, evW = nullptr, evW2 = nullptr, evKV = nullptr;
    static bool initDone = false;
    if (!initDone){
        cudaFuncSetAttribute(G_PROJ, cudaFuncAttributeMaxDynamicSharedMemorySize, S3H);
        cudaFuncSetAttribute(G_WO,   cudaFuncAttributeMaxDynamicSharedMemorySize, S3H);
        cudaFuncSetAttribute(G_FF1,  cudaFuncAttributeMaxDynamicSharedMemorySize, S3H);
        cudaFuncSetAttribute(attn,   cudaFuncAttributeMaxDynamicSharedMemorySize, AT_SMEM);
        cudaStreamCreateWithFlags(&s1, cudaStreamNonBlocking);
        cudaEventCreateWithFlags(&evRoot, cudaEventDisableTiming);
        cudaEventCreateWithFlags(&evW,    cudaEventDisableTiming);
        cudaEventCreateWithFlags(&evW2,   cudaEventDisableTiming);
        cudaEventCreateWithFlags(&evKV,   cudaEventDisableTiming);
        initDone = true;
    }

    dim3 tb(32, 8);
    dim3 gQKV(QKV/128, MROWS/128, 1);
    dim3 gKVc(1024/128,MROWS/128, 1);
    dim3 gCC (CC/128,  MROWS/128, 1);
    dim3 gFF (FF/128,  MROWS/128, 1);
    dim3 gAT (TT/128, BATCH*NHD);
    const int gLN = MROWS/8;   // warp-per-row LN

    // ===== fork side stream: prepass + cross K/V projection =====
    cudaEventRecord(evRoot, 0);
    cudaStreamWaitEvent(s1, evRoot, 0);
    wtrans8<<<dim3(16,16,8), tb, 0, s1>>>(Wq_s, Wk_s, Wv_s, Wo_s, Wq_c, Wk_c, Wv_c, Wo_c,
                                          p_wqs, p_wos, p_wqc, p_woc);
    cudaEventRecord(evW, s1);
    f2h_kernel<<<(MROWS*CC/4+255)/256, 256, 0, s1>>>(ca, p_ca, MROWS*CC/4);
    G_PROJ<<<gKVc,256,S3H,s1>>>(p_ca, CC, p_wqc + (size_t)CC*CC, CC, nullptr, nullptr,
                                p_kvc, 1024, CC);
    cudaEventRecord(evKV, s1);
    ttrans<<<dim3(FF/32, CC/32), tb, 0, s1>>>(Wf1, p_wf1, CC, FF);
    ttrans<<<dim3(CC/32, FF/32), tb, 0, s1>>>(Wf2, p_wf2, FF, CC);
    cudaEventRecord(evW2, s1);

    // ===== main chain (default stream) =====
    // self-attention
    ln_kernel<<<gLN,256>>>(x, g1, be1, p_ln);
    cudaStreamWaitEvent(0, evW, 0);
    G_PROJ<<<gQKV,256,S3H>>>(p_ln, CC, p_wqs, CC, nullptr, nullptr, p_qkv, QKV, CC);
    attn<<<gAT,256,AT_SMEM>>>(p_qkv, QKV, p_qkv + CC, p_qkv + 1024, QKV, x_m, p_att, 1);
    G_WO<<<gCC,256,S3H>>>(p_att, CC, p_wos, CC, bo_s, x, p_x1, CC, CC);

    // cross-attention
    ln_kernel<<<gLN,256>>>(p_x1, g2, be2, p_ln);
    G_PROJ<<<gCC,256,S3H>>>(p_ln, CC, p_wqc, CC, nullptr, nullptr, p_qc, CC, CC);
    cudaStreamWaitEvent(0, evKV, 0);
    attn<<<gAT,256,AT_SMEM>>>(p_qc, CC, p_kvc, p_kvc + CC, 1024, ca_m, p_att, 0);
    G_WO<<<gCC,256,S3H>>>(p_att, CC, p_woc, CC, bo_c, p_x1, p_x2, CC, CC);

    // feed-forward
    ln_kernel<<<gLN,256>>>(p_x2, g3, be3, p_ln);
    cudaStreamWaitEvent(0, evW2, 0);
    G_FF1<<<gFF,256,S3H>>>(p_ln, CC, p_wf1, CC, bf1, nullptr, p_h, FF, CC);
    G_WO <<<gCC,256,S3H>>>(p_h, FF, p_wf2, FF, bf2, p_x2, out, CC, FF);

    (void)in_sizes; (void)n_in; (void)out_size;
}